// round 3
// baseline (speedup 1.0000x reference)
#include <cuda_runtime.h>
#include <cuda_bf16.h>

#define N_NODES 10000
#define N_EDGES 320000
#define N_GRAPHS 64
#define FEAT 256
#define TOT_EDGES (N_EDGES + N_NODES)

// ---------------- scratch (static device globals; no allocation) ----------------
__device__ int   g_cnt[N_NODES];
__device__ int   g_rowptr[N_NODES + 1];
__device__ int   g_pos[N_NODES];
__device__ float g_dinv[N_NODES];
__device__ __align__(128) int   g_col[TOT_EDGES];
__device__ __align__(128) float g_w[TOT_EDGES];
__device__ float g_s1[N_NODES];
__device__ __align__(128) float g_pre2[N_NODES * FEAT];   // aggregated layer-1 output (pre-W2)
__device__ __align__(128) float g_out2[N_NODES * FEAT];   // relu(pre2 @ W2 + b2)

// ---------------- CSR build ----------------
__global__ void k_count_edges(const int* __restrict__ ei) {
    int e = blockIdx.x * blockDim.x + threadIdx.x;
    if (e < N_EDGES) {
        int dst = ei[N_EDGES + e];
        atomicAdd(&g_cnt[dst], 1);
    }
}

// single block: exclusive scan of (cnt+1) -> rowptr, plus dinv and pos
__global__ void k_scan() {
    __shared__ int sh[1024];
    int tid = threadIdx.x;
    const int per = (N_NODES + 1023) / 1024;
    int start = tid * per;
    int end = min(start + per, N_NODES);
    int s = 0;
    for (int i = start; i < end; i++) s += g_cnt[i] + 1;   // +1 self-loop
    sh[tid] = s;
    __syncthreads();
    for (int off = 1; off < 1024; off <<= 1) {
        int v = (tid >= off) ? sh[tid - off] : 0;
        __syncthreads();
        sh[tid] += v;
        __syncthreads();
    }
    int run = sh[tid] - s;  // exclusive prefix
    for (int i = start; i < end; i++) {
        g_rowptr[i] = run;
        g_pos[i] = run;
        g_dinv[i] = rsqrtf((float)(g_cnt[i] + 1));
        run += g_cnt[i] + 1;
    }
    if (end == N_NODES && start < N_NODES) g_rowptr[N_NODES] = run;
}

// fill edges + self-loops in one kernel
__global__ void k_fill(const int* __restrict__ ei) {
    int e = blockIdx.x * blockDim.x + threadIdx.x;
    if (e < N_EDGES) {
        int src = ei[e];
        int dst = ei[N_EDGES + e];
        int slot = atomicAdd(&g_pos[dst], 1);
        g_col[slot] = src;
        g_w[slot] = g_dinv[src];
    } else if (e < TOT_EDGES) {
        int i = e - N_EDGES;
        int slot = atomicAdd(&g_pos[i], 1);
        g_col[slot] = i;
        g_w[slot] = g_dinv[i];
    }
}

// ---------------- layer 1 aggregation (x is [N,1] -> scalar per node) ----------------
__global__ __launch_bounds__(256) void k_layer1_agg(const float* __restrict__ x) {
    int warp = (blockIdx.x * blockDim.x + threadIdx.x) >> 5;
    int lane = threadIdx.x & 31;
    if (warp >= N_NODES) return;
    int s0 = g_rowptr[warp], s1 = g_rowptr[warp + 1];
    float acc = 0.f;
    for (int s = s0 + lane; s < s1; s += 32)
        acc += g_w[s] * x[g_col[s]];
    #pragma unroll
    for (int off = 16; off > 0; off >>= 1)
        acc += __shfl_down_sync(0xFFFFFFFF, acc, off);
    if (lane == 0) g_s1[warp] = g_dinv[warp] * acc;
}

// ---------------- layer-2 aggregation, recomputing h1 on the fly ----------------
// pre2[d,c] = dinv[d] * sum_{s in N(d)} dinv[s] * relu(s1[s]*W1[c] + b1[c])
__global__ __launch_bounds__(256) void k_agg1(const float* __restrict__ W1,
                                              const float* __restrict__ b1) {
    int warp = (blockIdx.x * blockDim.x + threadIdx.x) >> 5;
    int lane = threadIdx.x & 31;
    if (warp >= N_NODES) return;

    int cbase = lane * 8;
    float4 w1a = *(const float4*)(W1 + cbase);
    float4 w1b = *(const float4*)(W1 + cbase + 4);
    float4 b1a = *(const float4*)(b1 + cbase);
    float4 b1b = *(const float4*)(b1 + cbase + 4);
    float W1r[8] = {w1a.x, w1a.y, w1a.z, w1a.w, w1b.x, w1b.y, w1b.z, w1b.w};
    float b1r[8] = {b1a.x, b1a.y, b1a.z, b1a.w, b1b.x, b1b.y, b1b.z, b1b.w};

    int s0 = g_rowptr[warp], s1e = g_rowptr[warp + 1];
    float acc[8] = {0.f, 0.f, 0.f, 0.f, 0.f, 0.f, 0.f, 0.f};

    for (int base = s0; base < s1e; base += 32) {
        int idx = base + lane;
        float sv = 0.f, wv = 0.f;
        if (idx < s1e) {
            int c = g_col[idx];
            wv = g_w[idx];
            sv = g_s1[c];
        }
        int cnt = min(32, s1e - base);
        for (int j = 0; j < cnt; j++) {
            float svj = __shfl_sync(0xFFFFFFFF, sv, j);
            float wvj = __shfl_sync(0xFFFFFFFF, wv, j);
            #pragma unroll
            for (int k = 0; k < 8; k++)
                acc[k] = fmaf(wvj, fmaxf(fmaf(svj, W1r[k], b1r[k]), 0.f), acc[k]);
        }
    }

    float dd = g_dinv[warp];
    float4 o0 = make_float4(dd * acc[0], dd * acc[1], dd * acc[2], dd * acc[3]);
    float4 o1 = make_float4(dd * acc[4], dd * acc[5], dd * acc[6], dd * acc[7]);
    float4* out = (float4*)(g_pre2 + (size_t)warp * FEAT + cbase);
    out[0] = o0;
    out[1] = o1;
}

// ---------------- SGEMM fused: out2 = relu(pre2 @ W2 + b2)   M=10000, N=K=256 ----------------
#define BM 64
#define BN 128
#define BK 16
#define TM 4
#define TN 8
__global__ __launch_bounds__(256) void k_sgemm(const float* __restrict__ B,
                                               const float* __restrict__ bias) {
    __shared__ float As_t[BK][BM];      // k-major
    __shared__ float Bs[BK][BN];
    const float* A = g_pre2;
    float* C = g_out2;
    int tx = threadIdx.x;
    int block_row = blockIdx.y * BM;
    int block_col = blockIdx.x * BN;
    int tr = tx >> 4;            // 0..15
    int tc = tx & 15;            // 0..15

    float acc[TM][TN];
    #pragma unroll
    for (int m = 0; m < TM; m++)
        #pragma unroll
        for (int n = 0; n < TN; n++) acc[m][n] = 0.f;

    int arow = tx >> 2;                // 0..63
    int acol = (tx & 3) << 2;          // 0,4,8,12

    for (int k0 = 0; k0 < FEAT; k0 += BK) {
        int gar = block_row + arow;
        float4 av = make_float4(0.f, 0.f, 0.f, 0.f);
        if (gar < N_NODES)
            av = *(const float4*)(A + (size_t)gar * FEAT + k0 + acol);
        As_t[acol + 0][arow] = av.x;
        As_t[acol + 1][arow] = av.y;
        As_t[acol + 2][arow] = av.z;
        As_t[acol + 3][arow] = av.w;
        #pragma unroll
        for (int i = 0; i < 2; i++) {
            int lin = tx + i * 256;         // 0..511
            int brow = lin >> 5;            // 0..15
            int bcol = (lin & 31) << 2;     // 0..124
            float4 bv = *(const float4*)(B + (size_t)(k0 + brow) * FEAT + block_col + bcol);
            *(float4*)&Bs[brow][bcol] = bv;
        }
        __syncthreads();
        #pragma unroll
        for (int kk = 0; kk < BK; kk++) {
            float4 a = *(const float4*)&As_t[kk][tr * TM];
            float4 blo = *(const float4*)&Bs[kk][tc * TN];
            float4 bhi = *(const float4*)&Bs[kk][tc * TN + 4];
            float av4[TM] = {a.x, a.y, a.z, a.w};
            float bv8[TN] = {blo.x, blo.y, blo.z, blo.w, bhi.x, bhi.y, bhi.z, bhi.w};
            #pragma unroll
            for (int m = 0; m < TM; m++)
                #pragma unroll
                for (int n = 0; n < TN; n++)
                    acc[m][n] = fmaf(av4[m], bv8[n], acc[m][n]);
        }
        __syncthreads();
    }

    float4 bias_lo = *(const float4*)(bias + block_col + tc * TN);
    float4 bias_hi = *(const float4*)(bias + block_col + tc * TN + 4);
    float bb[TN] = {bias_lo.x, bias_lo.y, bias_lo.z, bias_lo.w,
                    bias_hi.x, bias_hi.y, bias_hi.z, bias_hi.w};
    #pragma unroll
    for (int m = 0; m < TM; m++) {
        int row = block_row + tr * TM + m;
        if (row < N_NODES) {
            float4 o0, o1;
            o0.x = fmaxf(acc[m][0] + bb[0], 0.f);
            o0.y = fmaxf(acc[m][1] + bb[1], 0.f);
            o0.z = fmaxf(acc[m][2] + bb[2], 0.f);
            o0.w = fmaxf(acc[m][3] + bb[3], 0.f);
            o1.x = fmaxf(acc[m][4] + bb[4], 0.f);
            o1.y = fmaxf(acc[m][5] + bb[5], 0.f);
            o1.z = fmaxf(acc[m][6] + bb[6], 0.f);
            o1.w = fmaxf(acc[m][7] + bb[7], 0.f);
            float4* out = (float4*)(C + (size_t)row * FEAT + block_col + tc * TN);
            out[0] = o0;
            out[1] = o1;
        }
    }
}

// ---------------- fused mean-pool + MLP head (one block per graph) ----------------
__global__ __launch_bounds__(256) void k_pool_mlp(
    const int* __restrict__ batch,
    const float* __restrict__ W3, const float* __restrict__ b3,
    const float* __restrict__ W4, const float* __restrict__ b4,
    const float* __restrict__ W5, const float* __restrict__ b5,
    const float* __restrict__ W6, const float* __restrict__ b6,
    const float* __restrict__ W7, const float* __restrict__ b7,
    float* __restrict__ y)
{
    int g = blockIdx.x;
    int t = threadIdx.x;

    // inline binary search for [start, end) of this graph (all threads redundantly)
    int lo = 0, hi = N_NODES;
    while (lo < hi) { int mid = (lo + hi) >> 1; if (batch[mid] < g) lo = mid + 1; else hi = mid; }
    int s = lo;
    lo = 0; hi = N_NODES;
    while (lo < hi) { int mid = (lo + hi) >> 1; if (batch[mid] < g + 1) lo = mid + 1; else hi = mid; }
    int e = lo;

    __shared__ float v0[256];
    __shared__ float v1[128];
    __shared__ float v2[128];
    __shared__ float v3[64];
    __shared__ float v4[32];

    float acc = 0.f;
    for (int i = s; i < e; i++) acc += g_out2[(size_t)i * FEAT + t];
    v0[t] = acc / (float)max(e - s, 1);
    __syncthreads();

    if (t < 128) {
        float a = b3[t];
        #pragma unroll 4
        for (int k = 0; k < 256; k++) a += v0[k] * W3[k * 128 + t];
        v1[t] = fmaxf(a, 0.f);
    }
    __syncthreads();
    if (t < 128) {
        float a = b4[t];
        #pragma unroll 4
        for (int k = 0; k < 128; k++) a += v1[k] * W4[k * 128 + t];
        v2[t] = fmaxf(a, 0.f);
    }
    __syncthreads();
    if (t < 64) {
        float a = b5[t];
        #pragma unroll 4
        for (int k = 0; k < 128; k++) a += v2[k] * W5[k * 64 + t];
        v3[t] = fmaxf(a, 0.f);
    }
    __syncthreads();
    if (t < 32) {
        float a = b6[t];
        #pragma unroll 4
        for (int k = 0; k < 64; k++) a += v3[k] * W6[k * 32 + t];
        v4[t] = fmaxf(a, 0.f);
    }
    __syncthreads();
    if (t < 32) {
        float p = v4[t] * W7[t];
        #pragma unroll
        for (int off = 16; off > 0; off >>= 1)
            p += __shfl_down_sync(0xFFFFFFFF, p, off);
        if (t == 0) y[g] = p + b7[0];
    }
}

// ---------------- launch ----------------
extern "C" void kernel_launch(void* const* d_in, const int* in_sizes, int n_in,
                              void* d_out, int out_size) {
    const float* x     = (const float*)d_in[0];
    const int*   ei    = (const int*)d_in[1];
    const int*   batch = (const int*)d_in[2];
    const float* W1 = (const float*)d_in[3];
    const float* b1 = (const float*)d_in[4];
    const float* W2 = (const float*)d_in[5];
    const float* b2 = (const float*)d_in[6];
    const float* W3 = (const float*)d_in[7];
    const float* b3 = (const float*)d_in[8];
    const float* W4 = (const float*)d_in[9];
    const float* b4 = (const float*)d_in[10];
    const float* W5 = (const float*)d_in[11];
    const float* b5 = (const float*)d_in[12];
    const float* W6 = (const float*)d_in[13];
    const float* b6 = (const float*)d_in[14];
    const float* W7 = (const float*)d_in[15];
    const float* b7 = (const float*)d_in[16];
    float* y = (float*)d_out;

    void* cnt_ptr = nullptr;
    cudaGetSymbolAddress(&cnt_ptr, g_cnt);
    cudaMemsetAsync(cnt_ptr, 0, N_NODES * sizeof(int));

    const int nb_edges = (N_EDGES + 255) / 256;
    const int nb_tot   = (TOT_EDGES + 255) / 256;
    const int nb_warp_nodes = (N_NODES * 32 + 255) / 256;

    k_count_edges<<<nb_edges, 256>>>(ei);
    k_scan<<<1, 1024>>>();
    k_fill<<<nb_tot, 256>>>(ei);

    k_layer1_agg<<<nb_warp_nodes, 256>>>(x);
    k_agg1<<<nb_warp_nodes, 256>>>(W1, b1);

    dim3 gemm_grid(FEAT / BN, (N_NODES + BM - 1) / BM);
    k_sgemm<<<gemm_grid, 256>>>(W2, b2);

    k_pool_mlp<<<N_GRAPHS, 256>>>(batch, W3, b3, W4, b4, W5, b5, W6, b6, W7, b7, y);
}

// round 4
// speedup vs baseline: 1.1500x; 1.1500x over previous
#include <cuda_runtime.h>
#include <cuda_bf16.h>

#define N_NODES 10000
#define N_EDGES 320000
#define N_GRAPHS 64
#define FEAT 256
#define TOT_EDGES (N_EDGES + N_NODES)

// ---------------- scratch (static device globals; no allocation) ----------------
__device__ int   g_cnt[N_NODES];
__device__ int   g_rowptr[N_NODES + 1];
__device__ int   g_pos[N_NODES];
__device__ float g_dinv[N_NODES];
__device__ __align__(128) int   g_col[TOT_EDGES];
__device__ __align__(128) float g_w[TOT_EDGES];
__device__ float g_s1[N_NODES];
__device__ __align__(128) float g_theta[FEAT];                  // sorted breakpoints
__device__ __align__(128) float g_U[(FEAT + 1) * FEAT];         // prefix slope table
__device__ __align__(128) float g_V[(FEAT + 1) * FEAT];         // prefix intercept table
__device__ __align__(128) float g_h[N_NODES * FEAT];            // g(s1[s]) per node
__device__ __align__(128) float g_out2[N_NODES * FEAT];         // relu(agg + b2)

// ---------------- CSR build ----------------
__global__ void k_count_edges(const int* __restrict__ ei) {
    int e = blockIdx.x * blockDim.x + threadIdx.x;
    if (e < N_EDGES) {
        int dst = ei[N_EDGES + e];
        atomicAdd(&g_cnt[dst], 1);
    }
}

// single block: exclusive scan of (cnt+1) -> rowptr, plus dinv and pos
__global__ void k_scan() {
    __shared__ int sh[1024];
    int tid = threadIdx.x;
    const int per = (N_NODES + 1023) / 1024;
    int start = tid * per;
    int end = min(start + per, N_NODES);
    int s = 0;
    for (int i = start; i < end; i++) s += g_cnt[i] + 1;   // +1 self-loop
    sh[tid] = s;
    __syncthreads();
    for (int off = 1; off < 1024; off <<= 1) {
        int v = (tid >= off) ? sh[tid - off] : 0;
        __syncthreads();
        sh[tid] += v;
        __syncthreads();
    }
    int run = sh[tid] - s;  // exclusive prefix
    for (int i = start; i < end; i++) {
        g_rowptr[i] = run;
        g_pos[i] = run;
        g_dinv[i] = rsqrtf((float)(g_cnt[i] + 1));
        run += g_cnt[i] + 1;
    }
    if (end == N_NODES && start < N_NODES) g_rowptr[N_NODES] = run;
}

// fill edges + self-loops in one kernel
__global__ void k_fill(const int* __restrict__ ei) {
    int e = blockIdx.x * blockDim.x + threadIdx.x;
    if (e < N_EDGES) {
        int src = ei[e];
        int dst = ei[N_EDGES + e];
        int slot = atomicAdd(&g_pos[dst], 1);
        g_col[slot] = src;
        g_w[slot] = g_dinv[src];
    } else if (e < TOT_EDGES) {
        int i = e - N_EDGES;
        int slot = atomicAdd(&g_pos[i], 1);
        g_col[slot] = i;
        g_w[slot] = g_dinv[i];
    }
}

// ---------------- layer 1 aggregation (x is [N,1] -> scalar per node) ----------------
__global__ __launch_bounds__(256) void k_layer1_agg(const float* __restrict__ x) {
    int warp = (blockIdx.x * blockDim.x + threadIdx.x) >> 5;
    int lane = threadIdx.x & 31;
    if (warp >= N_NODES) return;
    int s0 = g_rowptr[warp], s1 = g_rowptr[warp + 1];
    float acc = 0.f;
    for (int s = s0 + lane; s < s1; s += 32)
        acc += g_w[s] * x[g_col[s]];
    #pragma unroll
    for (int off = 16; off > 0; off >>= 1)
        acc += __shfl_down_sync(0xFFFFFFFF, acc, off);
    if (lane == 0) g_s1[warp] = g_dinv[warp] * acc;
}

// ---------------- build piecewise-linear tables for g(t) = relu(t*W1+b1) @ W2 ----------------
// Events: channel c with W1[c]>0 activates at theta=-b1/W1 (payload c);
//         W1[c]<0 deactivates at theta (payload 256+c), active at -inf;
//         W1[c]==0: constant; if b1>0 folded into base (payload 1024, theta=+inf).
// Sorted thetas -> g_theta. Prefix tables: U[k],V[k] = slope/intercept vectors valid
// for t in (theta[k-1], theta[k]).  g(t) = t*U[k(t)] + V[k(t)], k(t) = #{theta_i < t}.
__global__ __launch_bounds__(256) void k_table(const float* __restrict__ W1,
                                               const float* __restrict__ b1,
                                               const float* __restrict__ W2) {
    __shared__ float key[FEAT];
    __shared__ int   pay[FEAT];
    __shared__ float sW1[FEAT];
    __shared__ float sB1[FEAT];
    int t = threadIdx.x;

    float w = W1[t];
    float bb = b1[t];
    sW1[t] = w;
    sB1[t] = bb;
    if (w > 0.f)      { key[t] = -bb / w; pay[t] = t; }
    else if (w < 0.f) { key[t] = -bb / w; pay[t] = 256 + t; }
    else              { key[t] = 1e30f;   pay[t] = 1024; }
    __syncthreads();

    // bitonic sort 256 elements
    for (int size = 2; size <= FEAT; size <<= 1) {
        for (int stride = size >> 1; stride > 0; stride >>= 1) {
            __syncthreads();
            int j = t ^ stride;
            if (j > t) {
                bool ascending = ((t & size) == 0);
                float a = key[t], b = key[j];
                if ((a > b) == ascending) {
                    key[t] = b; key[j] = a;
                    int tmp = pay[t]; pay[t] = pay[j]; pay[j] = tmp;
                }
            }
        }
    }
    __syncthreads();
    g_theta[t] = key[t];

    // base: channels active at t = -inf
    int jf = t;   // this thread owns output feature jf
    float u = 0.f, v = 0.f;
    #pragma unroll 4
    for (int c = 0; c < FEAT; c++) {
        float wc = sW1[c], bc = sB1[c];
        float w2 = W2[c * FEAT + jf];
        if (wc < 0.f)                    { u += wc * w2; v += bc * w2; }
        else if (wc == 0.f && bc > 0.f)  { v += bc * w2; }
    }
    g_U[jf] = u;
    g_V[jf] = v;

    // prefix scan over sorted events
    #pragma unroll 8
    for (int k = 0; k < FEAT; k++) {
        int p = pay[k];
        int c = p & 255;
        float sgn = (p < 256) ? 1.f : ((p < 512) ? -1.f : 0.f);
        float w2 = W2[c * FEAT + jf];
        u += sgn * (sW1[c] * w2);
        v += sgn * (sB1[c] * w2);
        g_U[(k + 1) * FEAT + jf] = u;
        g_V[(k + 1) * FEAT + jf] = v;
    }
}

// ---------------- per-node h = g(s1[node]) via table lookup ----------------
__global__ __launch_bounds__(256) void k_h() {
    __shared__ float th[FEAT];
    int tid = threadIdx.x;
    th[tid] = g_theta[tid];
    __syncthreads();

    int warp = (blockIdx.x * blockDim.x + tid) >> 5;
    int lane = tid & 31;
    if (warp >= N_NODES) return;

    float t = g_s1[warp];
    // k = #{theta < t}
    int lo = 0, hi = FEAT;
    while (lo < hi) { int m = (lo + hi) >> 1; if (th[m] < t) lo = m + 1; else hi = m; }
    int k = lo;

    const float* Urow = g_U + (size_t)k * FEAT + lane * 8;
    const float* Vrow = g_V + (size_t)k * FEAT + lane * 8;
    float4 u0 = *(const float4*)(Urow);
    float4 u1 = *(const float4*)(Urow + 4);
    float4 v0 = *(const float4*)(Vrow);
    float4 v1 = *(const float4*)(Vrow + 4);
    float4 o0, o1;
    o0.x = fmaf(t, u0.x, v0.x); o0.y = fmaf(t, u0.y, v0.y);
    o0.z = fmaf(t, u0.z, v0.z); o0.w = fmaf(t, u0.w, v0.w);
    o1.x = fmaf(t, u1.x, v1.x); o1.y = fmaf(t, u1.y, v1.y);
    o1.z = fmaf(t, u1.z, v1.z); o1.w = fmaf(t, u1.w, v1.w);
    float4* out = (float4*)(g_h + (size_t)warp * FEAT + lane * 8);
    out[0] = o0;
    out[1] = o1;
}

// ---------------- SpMM gather: out2 = relu(dinv[d]*sum(w*h[src]) + b2) ----------------
__global__ __launch_bounds__(256) void k_spmm(const float* __restrict__ b2) {
    int warp = (blockIdx.x * blockDim.x + threadIdx.x) >> 5;
    int lane = threadIdx.x & 31;
    if (warp >= N_NODES) return;
    int s0 = g_rowptr[warp], s1 = g_rowptr[warp + 1];
    float acc[8] = {0.f, 0.f, 0.f, 0.f, 0.f, 0.f, 0.f, 0.f};
    const float* h = g_h;
    int s = s0;
    for (; s + 1 < s1; s += 2) {
        int c0 = g_col[s], c1 = g_col[s + 1];
        float w0 = g_w[s], w1 = g_w[s + 1];
        const float4* r0 = (const float4*)(h + (size_t)c0 * FEAT + lane * 8);
        const float4* r1 = (const float4*)(h + (size_t)c1 * FEAT + lane * 8);
        float4 a0 = r0[0], d0 = r0[1];
        float4 a1 = r1[0], d1 = r1[1];
        acc[0] += w0 * a0.x; acc[1] += w0 * a0.y; acc[2] += w0 * a0.z; acc[3] += w0 * a0.w;
        acc[4] += w0 * d0.x; acc[5] += w0 * d0.y; acc[6] += w0 * d0.z; acc[7] += w0 * d0.w;
        acc[0] += w1 * a1.x; acc[1] += w1 * a1.y; acc[2] += w1 * a1.z; acc[3] += w1 * a1.w;
        acc[4] += w1 * d1.x; acc[5] += w1 * d1.y; acc[6] += w1 * d1.z; acc[7] += w1 * d1.w;
    }
    if (s < s1) {
        int c0 = g_col[s];
        float w0 = g_w[s];
        const float4* r0 = (const float4*)(h + (size_t)c0 * FEAT + lane * 8);
        float4 a0 = r0[0], d0 = r0[1];
        acc[0] += w0 * a0.x; acc[1] += w0 * a0.y; acc[2] += w0 * a0.z; acc[3] += w0 * a0.w;
        acc[4] += w0 * d0.x; acc[5] += w0 * d0.y; acc[6] += w0 * d0.z; acc[7] += w0 * d0.w;
    }
    float dd = g_dinv[warp];
    int cbase = lane * 8;
    float4 o0, o1;
    o0.x = fmaxf(dd * acc[0] + b2[cbase + 0], 0.f);
    o0.y = fmaxf(dd * acc[1] + b2[cbase + 1], 0.f);
    o0.z = fmaxf(dd * acc[2] + b2[cbase + 2], 0.f);
    o0.w = fmaxf(dd * acc[3] + b2[cbase + 3], 0.f);
    o1.x = fmaxf(dd * acc[4] + b2[cbase + 4], 0.f);
    o1.y = fmaxf(dd * acc[5] + b2[cbase + 5], 0.f);
    o1.z = fmaxf(dd * acc[6] + b2[cbase + 6], 0.f);
    o1.w = fmaxf(dd * acc[7] + b2[cbase + 7], 0.f);
    float4* out = (float4*)(g_out2 + (size_t)warp * FEAT + cbase);
    out[0] = o0;
    out[1] = o1;
}

// ---------------- fused mean-pool + MLP head (one block per graph) ----------------
__global__ __launch_bounds__(256) void k_pool_mlp(
    const int* __restrict__ batch,
    const float* __restrict__ W3, const float* __restrict__ b3,
    const float* __restrict__ W4, const float* __restrict__ b4,
    const float* __restrict__ W5, const float* __restrict__ b5,
    const float* __restrict__ W6, const float* __restrict__ b6,
    const float* __restrict__ W7, const float* __restrict__ b7,
    float* __restrict__ y)
{
    int g = blockIdx.x;
    int t = threadIdx.x;

    int lo = 0, hi = N_NODES;
    while (lo < hi) { int mid = (lo + hi) >> 1; if (batch[mid] < g) lo = mid + 1; else hi = mid; }
    int s = lo;
    lo = 0; hi = N_NODES;
    while (lo < hi) { int mid = (lo + hi) >> 1; if (batch[mid] < g + 1) lo = mid + 1; else hi = mid; }
    int e = lo;

    __shared__ float v0[256];
    __shared__ float v1[128];
    __shared__ float v2[128];
    __shared__ float v3[64];
    __shared__ float v4[32];

    float acc = 0.f;
    for (int i = s; i < e; i++) acc += g_out2[(size_t)i * FEAT + t];
    v0[t] = acc / (float)max(e - s, 1);
    __syncthreads();

    if (t < 128) {
        float a = b3[t];
        #pragma unroll 4
        for (int k = 0; k < 256; k++) a += v0[k] * W3[k * 128 + t];
        v1[t] = fmaxf(a, 0.f);
    }
    __syncthreads();
    if (t < 128) {
        float a = b4[t];
        #pragma unroll 4
        for (int k = 0; k < 128; k++) a += v1[k] * W4[k * 128 + t];
        v2[t] = fmaxf(a, 0.f);
    }
    __syncthreads();
    if (t < 64) {
        float a = b5[t];
        #pragma unroll 4
        for (int k = 0; k < 128; k++) a += v2[k] * W5[k * 64 + t];
        v3[t] = fmaxf(a, 0.f);
    }
    __syncthreads();
    if (t < 32) {
        float a = b6[t];
        #pragma unroll 4
        for (int k = 0; k < 64; k++) a += v3[k] * W6[k * 32 + t];
        v4[t] = fmaxf(a, 0.f);
    }
    __syncthreads();
    if (t < 32) {
        float p = v4[t] * W7[t];
        #pragma unroll
        for (int off = 16; off > 0; off >>= 1)
            p += __shfl_down_sync(0xFFFFFFFF, p, off);
        if (t == 0) y[g] = p + b7[0];
    }
}

// ---------------- launch ----------------
extern "C" void kernel_launch(void* const* d_in, const int* in_sizes, int n_in,
                              void* d_out, int out_size) {
    const float* x     = (const float*)d_in[0];
    const int*   ei    = (const int*)d_in[1];
    const int*   batch = (const int*)d_in[2];
    const float* W1 = (const float*)d_in[3];
    const float* b1 = (const float*)d_in[4];
    const float* W2 = (const float*)d_in[5];
    const float* b2 = (const float*)d_in[6];
    const float* W3 = (const float*)d_in[7];
    const float* b3 = (const float*)d_in[8];
    const float* W4 = (const float*)d_in[9];
    const float* b4 = (const float*)d_in[10];
    const float* W5 = (const float*)d_in[11];
    const float* b5 = (const float*)d_in[12];
    const float* W6 = (const float*)d_in[13];
    const float* b6 = (const float*)d_in[14];
    const float* W7 = (const float*)d_in[15];
    const float* b7 = (const float*)d_in[16];
    float* y = (float*)d_out;

    void* cnt_ptr = nullptr;
    cudaGetSymbolAddress(&cnt_ptr, g_cnt);
    cudaMemsetAsync(cnt_ptr, 0, N_NODES * sizeof(int));

    const int nb_edges = (N_EDGES + 255) / 256;
    const int nb_tot   = (TOT_EDGES + 255) / 256;
    const int nb_warp_nodes = (N_NODES * 32 + 255) / 256;

    k_count_edges<<<nb_edges, 256>>>(ei);
    k_scan<<<1, 1024>>>();
    k_fill<<<nb_tot, 256>>>(ei);

    k_layer1_agg<<<nb_warp_nodes, 256>>>(x);
    k_table<<<1, 256>>>(W1, b1, W2);
    k_h<<<nb_warp_nodes, 256>>>();
    k_spmm<<<nb_warp_nodes, 256>>>(b2);

    k_pool_mlp<<<N_GRAPHS, 256>>>(batch, W3, b3, W4, b4, W5, b5, W6, b6, W7, b7, y);
}

// round 5
// speedup vs baseline: 1.3634x; 1.1855x over previous
#include <cuda_runtime.h>
#include <cuda_bf16.h>

#define N_NODES 10000
#define N_EDGES 320000
#define N_GRAPHS 64
#define FEAT 256
#define TOT_EDGES (N_EDGES + N_NODES)

// ---------------- scratch (static device globals; no allocation) ----------------
__device__ int   g_cnt[N_NODES];
__device__ int   g_rowptr[N_NODES + 1];
__device__ int   g_pos[N_NODES];
__device__ float g_dinv[N_NODES];
__device__ __align__(128) int   g_col[TOT_EDGES];
__device__ __align__(128) float g_w[TOT_EDGES];
__device__ float g_s1[N_NODES];
__device__ __align__(128) float g_theta[FEAT];                  // sorted breakpoints
__device__ int   g_pay[FEAT];                                    // sorted payloads
__device__ __align__(128) float g_U[(FEAT + 1) * FEAT];         // prefix slope table
__device__ __align__(128) float g_V[(FEAT + 1) * FEAT];         // prefix intercept table
__device__ __align__(128) float g_h[N_NODES * FEAT];            // g(s1[s]) per node
__device__ __align__(128) float g_out2[N_NODES * FEAT];         // relu(agg + b2)

// ---------------- CSR build ----------------
__global__ void k_count_edges(const int* __restrict__ ei) {
    int e = blockIdx.x * blockDim.x + threadIdx.x;
    if (e < N_EDGES) {
        int dst = ei[N_EDGES + e];
        atomicAdd(&g_cnt[dst], 1);
    }
}

// single block: exclusive scan of (cnt+1) -> rowptr, plus dinv and pos
__global__ void k_scan() {
    __shared__ int sh[1024];
    int tid = threadIdx.x;
    const int per = (N_NODES + 1023) / 1024;
    int start = tid * per;
    int end = min(start + per, N_NODES);
    int s = 0;
    for (int i = start; i < end; i++) s += g_cnt[i] + 1;   // +1 self-loop
    sh[tid] = s;
    __syncthreads();
    for (int off = 1; off < 1024; off <<= 1) {
        int v = (tid >= off) ? sh[tid - off] : 0;
        __syncthreads();
        sh[tid] += v;
        __syncthreads();
    }
    int run = sh[tid] - s;  // exclusive prefix
    for (int i = start; i < end; i++) {
        g_rowptr[i] = run;
        g_pos[i] = run;
        g_dinv[i] = rsqrtf((float)(g_cnt[i] + 1));
        run += g_cnt[i] + 1;
    }
    if (end == N_NODES && start < N_NODES) g_rowptr[N_NODES] = run;
}

// fill edges + self-loops in one kernel
__global__ void k_fill(const int* __restrict__ ei) {
    int e = blockIdx.x * blockDim.x + threadIdx.x;
    if (e < N_EDGES) {
        int src = ei[e];
        int dst = ei[N_EDGES + e];
        int slot = atomicAdd(&g_pos[dst], 1);
        g_col[slot] = src;
        g_w[slot] = g_dinv[src];
    } else if (e < TOT_EDGES) {
        int i = e - N_EDGES;
        int slot = atomicAdd(&g_pos[i], 1);
        g_col[slot] = i;
        g_w[slot] = g_dinv[i];
    }
}

// ---------------- layer 1 aggregation (x is [N,1] -> scalar per node) ----------------
__global__ __launch_bounds__(256) void k_layer1_agg(const float* __restrict__ x) {
    int warp = (blockIdx.x * blockDim.x + threadIdx.x) >> 5;
    int lane = threadIdx.x & 31;
    if (warp >= N_NODES) return;
    int s0 = g_rowptr[warp], s1 = g_rowptr[warp + 1];
    float acc = 0.f;
    for (int s = s0 + lane; s < s1; s += 32)
        acc += g_w[s] * x[g_col[s]];
    #pragma unroll
    for (int off = 16; off > 0; off >>= 1)
        acc += __shfl_down_sync(0xFFFFFFFF, acc, off);
    if (lane == 0) g_s1[warp] = g_dinv[warp] * acc;
}

// ---------------- piecewise-linear tables for g(t) = relu(t*W1+b1) @ W2 ----------------
// Step 1: sort breakpoints (1 block, bitonic).
// Events: W1[c]>0 activates at theta=-b1/W1 (payload c); W1[c]<0 deactivates (payload 256+c),
// active at -inf; W1[c]==0 constant (payload 1024; b1>0 folded into base).
__global__ __launch_bounds__(256) void k_sort(const float* __restrict__ W1,
                                              const float* __restrict__ b1) {
    __shared__ float key[FEAT];
    __shared__ int   pay[FEAT];
    int t = threadIdx.x;
    float w = W1[t];
    float bb = b1[t];
    if (w > 0.f)      { key[t] = -bb / w; pay[t] = t; }
    else if (w < 0.f) { key[t] = -bb / w; pay[t] = 256 + t; }
    else              { key[t] = 1e30f;   pay[t] = 1024; }
    __syncthreads();
    for (int size = 2; size <= FEAT; size <<= 1) {
        for (int stride = size >> 1; stride > 0; stride >>= 1) {
            __syncthreads();
            int j = t ^ stride;
            if (j > t) {
                bool ascending = ((t & size) == 0);
                float a = key[t], b = key[j];
                if ((a > b) == ascending) {
                    key[t] = b; key[j] = a;
                    int tmp = pay[t]; pay[t] = pay[j]; pay[j] = tmp;
                }
            }
        }
    }
    __syncthreads();
    g_theta[t] = key[t];
    g_pay[t] = pay[t];
}

// Step 2: parallel prefix tables. 8 blocks x 256 threads.
// Block owns 32 output features jf = jf0..jf0+31 (lane = jf offset).
// Warp w owns event chunk [32w, 32w+32). Two-pass: totals -> offsets -> write.
__global__ __launch_bounds__(256) void k_prefix(const float* __restrict__ W1,
                                                const float* __restrict__ b1,
                                                const float* __restrict__ W2) {
    __shared__ int   s_pay[FEAT];
    __shared__ float s_W1[FEAT];
    __shared__ float s_b1[FEAT];
    __shared__ float s_bu[8][32];
    __shared__ float s_bv[8][32];
    __shared__ float s_tu[8][32];
    __shared__ float s_tv[8][32];

    int t = threadIdx.x;
    int lane = t & 31;
    int w = t >> 5;
    int jf = blockIdx.x * 32 + lane;

    s_pay[t] = g_pay[t];
    s_W1[t] = W1[t];
    s_b1[t] = b1[t];
    __syncthreads();

    // partial base over channels [32w, 32w+32)
    float bu = 0.f, bv = 0.f;
    #pragma unroll 4
    for (int i = 0; i < 32; i++) {
        int c = 32 * w + i;
        float wc = s_W1[c], bc = s_b1[c];
        float w2 = W2[c * FEAT + jf];
        if (wc < 0.f)                   { bu += wc * w2; bv += bc * w2; }
        else if (wc == 0.f && bc > 0.f) { bv += bc * w2; }
    }
    s_bu[w][lane] = bu;
    s_bv[w][lane] = bv;

    // pass 1: per-warp event-chunk totals
    float tu = 0.f, tv = 0.f;
    #pragma unroll 4
    for (int i = 0; i < 32; i++) {
        int k = 32 * w + i;
        int p = s_pay[k];
        int c = p & 255;
        float sgn = (p < 256) ? 1.f : ((p < 512) ? -1.f : 0.f);
        float w2 = W2[c * FEAT + jf];
        tu += sgn * (s_W1[c] * w2);
        tv += sgn * (s_b1[c] * w2);
    }
    s_tu[w][lane] = tu;
    s_tv[w][lane] = tv;
    __syncthreads();

    // offsets: full base + totals of prior warps
    float offu = 0.f, offv = 0.f;
    #pragma unroll
    for (int i = 0; i < 8; i++) { offu += s_bu[i][lane]; offv += s_bv[i][lane]; }
    if (w == 0) {   // row 0 = base
        g_U[jf] = offu;
        g_V[jf] = offv;
    }
    #pragma unroll
    for (int i = 0; i < 8; i++) {
        if (i < w) { offu += s_tu[i][lane]; offv += s_tv[i][lane]; }
    }

    // pass 2: serial inclusive scan within chunk, write rows (coalesced 128B per row)
    float ru = offu, rv = offv;
    #pragma unroll 4
    for (int i = 0; i < 32; i++) {
        int k = 32 * w + i;
        int p = s_pay[k];
        int c = p & 255;
        float sgn = (p < 256) ? 1.f : ((p < 512) ? -1.f : 0.f);
        float w2 = W2[c * FEAT + jf];
        ru += sgn * (s_W1[c] * w2);
        rv += sgn * (s_b1[c] * w2);
        g_U[(size_t)(k + 1) * FEAT + jf] = ru;
        g_V[(size_t)(k + 1) * FEAT + jf] = rv;
    }
}

// ---------------- per-node h = g(s1[node]) via table lookup ----------------
__global__ __launch_bounds__(256) void k_h() {
    __shared__ float th[FEAT];
    int tid = threadIdx.x;
    th[tid] = g_theta[tid];
    __syncthreads();

    int warp = (blockIdx.x * blockDim.x + tid) >> 5;
    int lane = tid & 31;
    if (warp >= N_NODES) return;

    float t = g_s1[warp];
    int lo = 0, hi = FEAT;
    while (lo < hi) { int m = (lo + hi) >> 1; if (th[m] < t) lo = m + 1; else hi = m; }
    int k = lo;

    const float* Urow = g_U + (size_t)k * FEAT + lane * 8;
    const float* Vrow = g_V + (size_t)k * FEAT + lane * 8;
    float4 u0 = *(const float4*)(Urow);
    float4 u1 = *(const float4*)(Urow + 4);
    float4 v0 = *(const float4*)(Vrow);
    float4 v1 = *(const float4*)(Vrow + 4);
    float4 o0, o1;
    o0.x = fmaf(t, u0.x, v0.x); o0.y = fmaf(t, u0.y, v0.y);
    o0.z = fmaf(t, u0.z, v0.z); o0.w = fmaf(t, u0.w, v0.w);
    o1.x = fmaf(t, u1.x, v1.x); o1.y = fmaf(t, u1.y, v1.y);
    o1.z = fmaf(t, u1.z, v1.z); o1.w = fmaf(t, u1.w, v1.w);
    float4* out = (float4*)(g_h + (size_t)warp * FEAT + lane * 8);
    out[0] = o0;
    out[1] = o1;
}

// ---------------- SpMM gather: out2 = relu(dinv[d]*sum(w*h[src]) + b2) ----------------
__global__ __launch_bounds__(256) void k_spmm(const float* __restrict__ b2) {
    int warp = (blockIdx.x * blockDim.x + threadIdx.x) >> 5;
    int lane = threadIdx.x & 31;
    if (warp >= N_NODES) return;
    int s0 = g_rowptr[warp], s1 = g_rowptr[warp + 1];
    float acc[8] = {0.f, 0.f, 0.f, 0.f, 0.f, 0.f, 0.f, 0.f};
    const float* h = g_h;
    int s = s0;
    for (; s + 1 < s1; s += 2) {
        int c0 = g_col[s], c1 = g_col[s + 1];
        float w0 = g_w[s], w1 = g_w[s + 1];
        const float4* r0 = (const float4*)(h + (size_t)c0 * FEAT + lane * 8);
        const float4* r1 = (const float4*)(h + (size_t)c1 * FEAT + lane * 8);
        float4 a0 = r0[0], d0 = r0[1];
        float4 a1 = r1[0], d1 = r1[1];
        acc[0] += w0 * a0.x; acc[1] += w0 * a0.y; acc[2] += w0 * a0.z; acc[3] += w0 * a0.w;
        acc[4] += w0 * d0.x; acc[5] += w0 * d0.y; acc[6] += w0 * d0.z; acc[7] += w0 * d0.w;
        acc[0] += w1 * a1.x; acc[1] += w1 * a1.y; acc[2] += w1 * a1.z; acc[3] += w1 * a1.w;
        acc[4] += w1 * d1.x; acc[5] += w1 * d1.y; acc[6] += w1 * d1.z; acc[7] += w1 * d1.w;
    }
    if (s < s1) {
        int c0 = g_col[s];
        float w0 = g_w[s];
        const float4* r0 = (const float4*)(h + (size_t)c0 * FEAT + lane * 8);
        float4 a0 = r0[0], d0 = r0[1];
        acc[0] += w0 * a0.x; acc[1] += w0 * a0.y; acc[2] += w0 * a0.z; acc[3] += w0 * a0.w;
        acc[4] += w0 * d0.x; acc[5] += w0 * d0.y; acc[6] += w0 * d0.z; acc[7] += w0 * d0.w;
    }
    float dd = g_dinv[warp];
    int cbase = lane * 8;
    float4 o0, o1;
    o0.x = fmaxf(dd * acc[0] + b2[cbase + 0], 0.f);
    o0.y = fmaxf(dd * acc[1] + b2[cbase + 1], 0.f);
    o0.z = fmaxf(dd * acc[2] + b2[cbase + 2], 0.f);
    o0.w = fmaxf(dd * acc[3] + b2[cbase + 3], 0.f);
    o1.x = fmaxf(dd * acc[4] + b2[cbase + 4], 0.f);
    o1.y = fmaxf(dd * acc[5] + b2[cbase + 5], 0.f);
    o1.z = fmaxf(dd * acc[6] + b2[cbase + 6], 0.f);
    o1.w = fmaxf(dd * acc[7] + b2[cbase + 7], 0.f);
    float4* out = (float4*)(g_out2 + (size_t)warp * FEAT + cbase);
    out[0] = o0;
    out[1] = o1;
}

// ---------------- fused mean-pool + MLP head (one block per graph) ----------------
__global__ __launch_bounds__(256) void k_pool_mlp(
    const int* __restrict__ batch,
    const float* __restrict__ W3, const float* __restrict__ b3,
    const float* __restrict__ W4, const float* __restrict__ b4,
    const float* __restrict__ W5, const float* __restrict__ b5,
    const float* __restrict__ W6, const float* __restrict__ b6,
    const float* __restrict__ W7, const float* __restrict__ b7,
    float* __restrict__ y)
{
    int g = blockIdx.x;
    int t = threadIdx.x;

    int lo = 0, hi = N_NODES;
    while (lo < hi) { int mid = (lo + hi) >> 1; if (batch[mid] < g) lo = mid + 1; else hi = mid; }
    int s = lo;
    lo = 0; hi = N_NODES;
    while (lo < hi) { int mid = (lo + hi) >> 1; if (batch[mid] < g + 1) lo = mid + 1; else hi = mid; }
    int e = lo;

    __shared__ float v0[256];
    __shared__ float v1[128];
    __shared__ float v2[128];
    __shared__ float v3[64];
    __shared__ float v4[32];

    float acc = 0.f;
    for (int i = s; i < e; i++) acc += g_out2[(size_t)i * FEAT + t];
    v0[t] = acc / (float)max(e - s, 1);
    __syncthreads();

    if (t < 128) {
        float a = b3[t];
        #pragma unroll 4
        for (int k = 0; k < 256; k++) a += v0[k] * W3[k * 128 + t];
        v1[t] = fmaxf(a, 0.f);
    }
    __syncthreads();
    if (t < 128) {
        float a = b4[t];
        #pragma unroll 4
        for (int k = 0; k < 128; k++) a += v1[k] * W4[k * 128 + t];
        v2[t] = fmaxf(a, 0.f);
    }
    __syncthreads();
    if (t < 64) {
        float a = b5[t];
        #pragma unroll 4
        for (int k = 0; k < 128; k++) a += v2[k] * W5[k * 64 + t];
        v3[t] = fmaxf(a, 0.f);
    }
    __syncthreads();
    if (t < 32) {
        float a = b6[t];
        #pragma unroll 4
        for (int k = 0; k < 64; k++) a += v3[k] * W6[k * 32 + t];
        v4[t] = fmaxf(a, 0.f);
    }
    __syncthreads();
    if (t < 32) {
        float p = v4[t] * W7[t];
        #pragma unroll
        for (int off = 16; off > 0; off >>= 1)
            p += __shfl_down_sync(0xFFFFFFFF, p, off);
        if (t == 0) y[g] = p + b7[0];
    }
}

// ---------------- launch ----------------
extern "C" void kernel_launch(void* const* d_in, const int* in_sizes, int n_in,
                              void* d_out, int out_size) {
    const float* x     = (const float*)d_in[0];
    const int*   ei    = (const int*)d_in[1];
    const int*   batch = (const int*)d_in[2];
    const float* W1 = (const float*)d_in[3];
    const float* b1 = (const float*)d_in[4];
    const float* W2 = (const float*)d_in[5];
    const float* b2 = (const float*)d_in[6];
    const float* W3 = (const float*)d_in[7];
    const float* b3 = (const float*)d_in[8];
    const float* W4 = (const float*)d_in[9];
    const float* b4 = (const float*)d_in[10];
    const float* W5 = (const float*)d_in[11];
    const float* b5 = (const float*)d_in[12];
    const float* W6 = (const float*)d_in[13];
    const float* b6 = (const float*)d_in[14];
    const float* W7 = (const float*)d_in[15];
    const float* b7 = (const float*)d_in[16];
    float* y = (float*)d_out;

    void* cnt_ptr = nullptr;
    cudaGetSymbolAddress(&cnt_ptr, g_cnt);
    cudaMemsetAsync(cnt_ptr, 0, N_NODES * sizeof(int));

    const int nb_edges = (N_EDGES + 255) / 256;
    const int nb_tot   = (TOT_EDGES + 255) / 256;
    const int nb_warp_nodes = (N_NODES * 32 + 255) / 256;

    k_count_edges<<<nb_edges, 256>>>(ei);
    k_scan<<<1, 1024>>>();
    k_fill<<<nb_tot, 256>>>(ei);

    k_layer1_agg<<<nb_warp_nodes, 256>>>(x);
    k_sort<<<1, 256>>>(W1, b1);
    k_prefix<<<8, 256>>>(W1, b1, W2);
    k_h<<<nb_warp_nodes, 256>>>();
    k_spmm<<<nb_warp_nodes, 256>>>(b2);

    k_pool_mlp<<<N_GRAPHS, 256>>>(batch, W3, b3, W4, b4, W5, b5, W6, b6, W7, b7, y);
}

// round 7
// speedup vs baseline: 1.4972x; 1.0981x over previous
#include <cuda_runtime.h>
#include <cuda_fp16.h>

#define N_NODES 10000
#define N_EDGES 320000
#define N_GRAPHS 64
#define FEAT 256
#define TOT_EDGES (N_EDGES + N_NODES)

// ---------------- scratch (static device globals; zero-initialized at load) ----------------
__device__ int   g_cnt[N_NODES];          // zeroed at load; re-zeroed by k_fill each call
__device__ int   g_rowptr[N_NODES + 1];
__device__ int   g_pos[N_NODES];
__device__ float g_dinv[N_NODES];
__device__ __align__(128) int   g_col[TOT_EDGES];
__device__ __align__(128) float g_w[TOT_EDGES];
__device__ __align__(128) float g_theta[FEAT];                  // sorted breakpoints
__device__ __align__(128) float g_U[(FEAT + 1) * FEAT];         // prefix slope table
__device__ __align__(128) float g_V[(FEAT + 1) * FEAT];         // prefix intercept table
__device__ __align__(128) __half g_h[N_NODES * FEAT];           // g(s1[s]) per node (fp16)
__device__ __align__(128) float g_out2[N_NODES * FEAT];         // relu(agg + b2)

// ---------------- CSR build ----------------
__global__ void k_count_edges(const int* __restrict__ ei) {
    int e = blockIdx.x * blockDim.x + threadIdx.x;
    if (e < N_EDGES) {
        int dst = ei[N_EDGES + e];
        atomicAdd(&g_cnt[dst], 1);
    }
}

// single block: exclusive scan of (cnt+1) -> rowptr, plus dinv and pos
__global__ void k_scan() {
    __shared__ int sh[1024];
    int tid = threadIdx.x;
    const int per = (N_NODES + 1023) / 1024;
    int start = tid * per;
    int end = min(start + per, N_NODES);
    int s = 0;
    for (int i = start; i < end; i++) s += g_cnt[i] + 1;   // +1 self-loop
    sh[tid] = s;
    __syncthreads();
    for (int off = 1; off < 1024; off <<= 1) {
        int v = (tid >= off) ? sh[tid - off] : 0;
        __syncthreads();
        sh[tid] += v;
        __syncthreads();
    }
    int run = sh[tid] - s;  // exclusive prefix
    for (int i = start; i < end; i++) {
        g_rowptr[i] = run;
        g_pos[i] = run;
        g_dinv[i] = rsqrtf((float)(g_cnt[i] + 1));
        run += g_cnt[i] + 1;
    }
    if (end == N_NODES && start < N_NODES) g_rowptr[N_NODES] = run;
}

// fill edges + self-loops; also re-zero g_cnt for the next call
__global__ void k_fill(const int* __restrict__ ei) {
    int e = blockIdx.x * blockDim.x + threadIdx.x;
    if (e < N_EDGES) {
        int src = ei[e];
        int dst = ei[N_EDGES + e];
        int slot = atomicAdd(&g_pos[dst], 1);
        g_col[slot] = src;
        g_w[slot] = g_dinv[src];
    } else if (e < TOT_EDGES) {
        int i = e - N_EDGES;
        int slot = atomicAdd(&g_pos[i], 1);
        g_col[slot] = i;
        g_w[slot] = g_dinv[i];
    }
    if (e < N_NODES) g_cnt[e] = 0;   // nobody reads g_cnt in this kernel
}

// ---------------- piecewise-linear tables for g(t) = relu(t*W1+b1) @ W2 ----------------
// 8 blocks x 256 threads. Each block redundantly bitonic-sorts the 256 breakpoint
// events in smem, then builds prefix tables for its 32 output features.
// Events: W1[c]>0 activates at theta=-b1/W1 (payload c); W1[c]<0 deactivates
// (payload 256+c), active at -inf; W1[c]==0 constant (payload 1024; b1>0 in base).
__global__ __launch_bounds__(256) void k_sortprefix(const float* __restrict__ W1,
                                                    const float* __restrict__ b1,
                                                    const float* __restrict__ W2) {
    __shared__ float key[FEAT];
    __shared__ int   pay[FEAT];
    __shared__ float sW1[FEAT];
    __shared__ float sB1[FEAT];
    __shared__ float s_bu[8][32];
    __shared__ float s_bv[8][32];
    __shared__ float s_tu[8][32];
    __shared__ float s_tv[8][32];

    int t = threadIdx.x;
    float w = W1[t];
    float bb = b1[t];
    sW1[t] = w;
    sB1[t] = bb;
    if (w > 0.f)      { key[t] = -bb / w; pay[t] = t; }
    else if (w < 0.f) { key[t] = -bb / w; pay[t] = 256 + t; }
    else              { key[t] = 1e30f;   pay[t] = 1024; }
    __syncthreads();

    // bitonic sort 256 elements
    for (int size = 2; size <= FEAT; size <<= 1) {
        for (int stride = size >> 1; stride > 0; stride >>= 1) {
            __syncthreads();
            int j = t ^ stride;
            if (j > t) {
                bool ascending = ((t & size) == 0);
                float a = key[t], b = key[j];
                if ((a > b) == ascending) {
                    key[t] = b; key[j] = a;
                    int tmp = pay[t]; pay[t] = pay[j]; pay[j] = tmp;
                }
            }
        }
    }
    __syncthreads();
    if (blockIdx.x == 0) g_theta[t] = key[t];

    int lane = t & 31;
    int wp = t >> 5;
    int jf = blockIdx.x * 32 + lane;

    // partial base over channels [32wp, 32wp+32)
    float bu = 0.f, bv = 0.f;
    #pragma unroll 4
    for (int i = 0; i < 32; i++) {
        int c = 32 * wp + i;
        float wc = sW1[c], bc = sB1[c];
        float w2 = W2[c * FEAT + jf];
        if (wc < 0.f)                   { bu += wc * w2; bv += bc * w2; }
        else if (wc == 0.f && bc > 0.f) { bv += bc * w2; }
    }
    s_bu[wp][lane] = bu;
    s_bv[wp][lane] = bv;

    // pass 1: per-warp event-chunk totals
    float tu = 0.f, tv = 0.f;
    #pragma unroll 4
    for (int i = 0; i < 32; i++) {
        int k = 32 * wp + i;
        int p = pay[k];
        int c = p & 255;
        float sgn = (p < 256) ? 1.f : ((p < 512) ? -1.f : 0.f);
        float w2 = W2[c * FEAT + jf];
        tu += sgn * (sW1[c] * w2);
        tv += sgn * (sB1[c] * w2);
    }
    s_tu[wp][lane] = tu;
    s_tv[wp][lane] = tv;
    __syncthreads();

    // offsets: full base + totals of prior warps
    float offu = 0.f, offv = 0.f;
    #pragma unroll
    for (int i = 0; i < 8; i++) { offu += s_bu[i][lane]; offv += s_bv[i][lane]; }
    if (wp == 0) {   // row 0 = base
        g_U[jf] = offu;
        g_V[jf] = offv;
    }
    #pragma unroll
    for (int i = 0; i < 8; i++) {
        if (i < wp) { offu += s_tu[i][lane]; offv += s_tv[i][lane]; }
    }

    // pass 2: serial inclusive scan within chunk, write rows (coalesced per row)
    float ru = offu, rv = offv;
    #pragma unroll 4
    for (int i = 0; i < 32; i++) {
        int k = 32 * wp + i;
        int p = pay[k];
        int c = p & 255;
        float sgn = (p < 256) ? 1.f : ((p < 512) ? -1.f : 0.f);
        float w2 = W2[c * FEAT + jf];
        ru += sgn * (sW1[c] * w2);
        rv += sgn * (sB1[c] * w2);
        g_U[(size_t)(k + 1) * FEAT + jf] = ru;
        g_V[(size_t)(k + 1) * FEAT + jf] = rv;
    }
}

// ---------------- fused: s1 = dinv*CSR-reduce(x), then h = g(s1) via table ----------------
__global__ __launch_bounds__(256) void k_l1h(const float* __restrict__ x) {
    __shared__ float th[FEAT];
    int tid = threadIdx.x;
    th[tid] = g_theta[tid];
    __syncthreads();

    int warp = (blockIdx.x * blockDim.x + tid) >> 5;
    int lane = tid & 31;
    if (warp >= N_NODES) return;

    int s0 = g_rowptr[warp], s1e = g_rowptr[warp + 1];
    float acc = 0.f;
    for (int s = s0 + lane; s < s1e; s += 32)
        acc += g_w[s] * x[g_col[s]];
    #pragma unroll
    for (int off = 16; off > 0; off >>= 1)
        acc += __shfl_xor_sync(0xFFFFFFFF, acc, off);
    float t = g_dinv[warp] * acc;   // all lanes have it

    int lo = 0, hi = FEAT;
    while (lo < hi) { int m = (lo + hi) >> 1; if (th[m] < t) lo = m + 1; else hi = m; }
    int k = lo;

    const float* Urow = g_U + (size_t)k * FEAT + lane * 8;
    const float* Vrow = g_V + (size_t)k * FEAT + lane * 8;
    float4 u0 = *(const float4*)(Urow);
    float4 u1 = *(const float4*)(Urow + 4);
    float4 v0 = *(const float4*)(Vrow);
    float4 v1 = *(const float4*)(Vrow + 4);
    __half2 h01 = __floats2half2_rn(fmaf(t, u0.x, v0.x), fmaf(t, u0.y, v0.y));
    __half2 h23 = __floats2half2_rn(fmaf(t, u0.z, v0.z), fmaf(t, u0.w, v0.w));
    __half2 h45 = __floats2half2_rn(fmaf(t, u1.x, v1.x), fmaf(t, u1.y, v1.y));
    __half2 h67 = __floats2half2_rn(fmaf(t, u1.z, v1.z), fmaf(t, u1.w, v1.w));
    uint4 packed;
    packed.x = *reinterpret_cast<unsigned int*>(&h01);
    packed.y = *reinterpret_cast<unsigned int*>(&h23);
    packed.z = *reinterpret_cast<unsigned int*>(&h45);
    packed.w = *reinterpret_cast<unsigned int*>(&h67);
    *(uint4*)(g_h + (size_t)warp * FEAT + lane * 8) = packed;
}

// ---------------- SpMM gather (fp16 rows): out2 = relu(dinv[d]*sum(w*h[src]) + b2) ----------------
__device__ __forceinline__ void spmm_accum(uint4 v, float w, float* acc) {
    __half2 q0 = *reinterpret_cast<__half2*>(&v.x);
    __half2 q1 = *reinterpret_cast<__half2*>(&v.y);
    __half2 q2 = *reinterpret_cast<__half2*>(&v.z);
    __half2 q3 = *reinterpret_cast<__half2*>(&v.w);
    float2 p0 = __half22float2(q0);
    float2 p1 = __half22float2(q1);
    float2 p2 = __half22float2(q2);
    float2 p3 = __half22float2(q3);
    acc[0] = fmaf(w, p0.x, acc[0]); acc[1] = fmaf(w, p0.y, acc[1]);
    acc[2] = fmaf(w, p1.x, acc[2]); acc[3] = fmaf(w, p1.y, acc[3]);
    acc[4] = fmaf(w, p2.x, acc[4]); acc[5] = fmaf(w, p2.y, acc[5]);
    acc[6] = fmaf(w, p3.x, acc[6]); acc[7] = fmaf(w, p3.y, acc[7]);
}

__global__ __launch_bounds__(256) void k_spmm(const float* __restrict__ b2) {
    int warp = (blockIdx.x * blockDim.x + threadIdx.x) >> 5;
    int lane = threadIdx.x & 31;
    if (warp >= N_NODES) return;
    int s0 = g_rowptr[warp], s1 = g_rowptr[warp + 1];
    float acc[8] = {0.f, 0.f, 0.f, 0.f, 0.f, 0.f, 0.f, 0.f};
    int s = s0;
    for (; s + 1 < s1; s += 2) {
        int c0 = g_col[s], c1 = g_col[s + 1];
        float w0 = g_w[s], w1 = g_w[s + 1];
        uint4 v0 = *(const uint4*)(g_h + (size_t)c0 * FEAT + lane * 8);
        uint4 v1 = *(const uint4*)(g_h + (size_t)c1 * FEAT + lane * 8);
        spmm_accum(v0, w0, acc);
        spmm_accum(v1, w1, acc);
    }
    if (s < s1) {
        int c0 = g_col[s];
        float w0 = g_w[s];
        uint4 v0 = *(const uint4*)(g_h + (size_t)c0 * FEAT + lane * 8);
        spmm_accum(v0, w0, acc);
    }
    float dd = g_dinv[warp];
    int cbase = lane * 8;
    float4 o0, o1;
    o0.x = fmaxf(dd * acc[0] + b2[cbase + 0], 0.f);
    o0.y = fmaxf(dd * acc[1] + b2[cbase + 1], 0.f);
    o0.z = fmaxf(dd * acc[2] + b2[cbase + 2], 0.f);
    o0.w = fmaxf(dd * acc[3] + b2[cbase + 3], 0.f);
    o1.x = fmaxf(dd * acc[4] + b2[cbase + 4], 0.f);
    o1.y = fmaxf(dd * acc[5] + b2[cbase + 5], 0.f);
    o1.z = fmaxf(dd * acc[6] + b2[cbase + 6], 0.f);
    o1.w = fmaxf(dd * acc[7] + b2[cbase + 7], 0.f);
    float4* out = (float4*)(g_out2 + (size_t)warp * FEAT + cbase);
    out[0] = o0;
    out[1] = o1;
}

// ---------------- fused mean-pool + MLP head (one block per graph) ----------------
__global__ __launch_bounds__(256) void k_pool_mlp(
    const int* __restrict__ batch,
    const float* __restrict__ W3, const float* __restrict__ b3,
    const float* __restrict__ W4, const float* __restrict__ b4,
    const float* __restrict__ W5, const float* __restrict__ b5,
    const float* __restrict__ W6, const float* __restrict__ b6,
    const float* __restrict__ W7, const float* __restrict__ b7,
    float* __restrict__ y)
{
    int g = blockIdx.x;
    int t = threadIdx.x;

    int lo = 0, hi = N_NODES;
    while (lo < hi) { int mid = (lo + hi) >> 1; if (batch[mid] < g) lo = mid + 1; else hi = mid; }
    int s = lo;
    lo = 0; hi = N_NODES;
    while (lo < hi) { int mid = (lo + hi) >> 1; if (batch[mid] < g + 1) lo = mid + 1; else hi = mid; }
    int e = lo;

    __shared__ float v0[256];
    __shared__ float v1[128];
    __shared__ float v2[128];
    __shared__ float v3[64];
    __shared__ float v4[32];

    float acc = 0.f;
    for (int i = s; i < e; i++) acc += g_out2[(size_t)i * FEAT + t];
    v0[t] = acc / (float)max(e - s, 1);
    __syncthreads();

    if (t < 128) {
        float a = b3[t];
        #pragma unroll 4
        for (int k = 0; k < 256; k++) a += v0[k] * W3[k * 128 + t];
        v1[t] = fmaxf(a, 0.f);
    }
    __syncthreads();
    if (t < 128) {
        float a = b4[t];
        #pragma unroll 4
        for (int k = 0; k < 128; k++) a += v1[k] * W4[k * 128 + t];
        v2[t] = fmaxf(a, 0.f);
    }
    __syncthreads();
    if (t < 64) {
        float a = b5[t];
        #pragma unroll 4
        for (int k = 0; k < 128; k++) a += v2[k] * W5[k * 64 + t];
        v3[t] = fmaxf(a, 0.f);
    }
    __syncthreads();
    if (t < 32) {
        float a = b6[t];
        #pragma unroll 4
        for (int k = 0; k < 64; k++) a += v3[k] * W6[k * 32 + t];
        v4[t] = fmaxf(a, 0.f);
    }
    __syncthreads();
    if (t < 32) {
        float p = v4[t] * W7[t];
        #pragma unroll
        for (int off = 16; off > 0; off >>= 1)
            p += __shfl_down_sync(0xFFFFFFFF, p, off);
        if (t == 0) y[g] = p + b7[0];
    }
}

// ---------------- launch ----------------
extern "C" void kernel_launch(void* const* d_in, const int* in_sizes, int n_in,
                              void* d_out, int out_size) {
    const float* x     = (const float*)d_in[0];
    const int*   ei    = (const int*)d_in[1];
    const int*   batch = (const int*)d_in[2];
    const float* W1 = (const float*)d_in[3];
    const float* b1 = (const float*)d_in[4];
    const float* W2 = (const float*)d_in[5];
    const float* b2 = (const float*)d_in[6];
    const float* W3 = (const float*)d_in[7];
    const float* b3 = (const float*)d_in[8];
    const float* W4 = (const float*)d_in[9];
    const float* b4 = (const float*)d_in[10];
    const float* W5 = (const float*)d_in[11];
    const float* b5 = (const float*)d_in[12];
    const float* W6 = (const float*)d_in[13];
    const float* b6 = (const float*)d_in[14];
    const float* W7 = (const float*)d_in[15];
    const float* b7 = (const float*)d_in[16];
    float* y = (float*)d_out;

    const int nb_edges = (N_EDGES + 255) / 256;
    const int nb_tot   = (TOT_EDGES + 255) / 256;
    const int nb_warp_nodes = (N_NODES * 32 + 255) / 256;

    k_count_edges<<<nb_edges, 256>>>(ei);
    k_scan<<<1, 1024>>>();
    k_fill<<<nb_tot, 256>>>(ei);
    k_sortprefix<<<8, 256>>>(W1, b1, W2);
    k_l1h<<<nb_warp_nodes, 256>>>(x);
    k_spmm<<<nb_warp_nodes, 256>>>(b2);
    k_pool_mlp<<<N_GRAPHS, 256>>>(batch, W3, b3, W4, b4, W5, b5, W6, b6, W7, b7, y);
}